// round 9
// baseline (speedup 1.0000x reference)
#include <cuda_runtime.h>
#include <cuda_fp16.h>
#include <cstdint>

// Problem constants
static constexpr int HID  = 1024;
static constexpr int NB   = 4;
static constexpr int SEQ  = 2048;
static constexpr int ROWS = NB * SEQ; // 8192

// ---------------------------------------------------------------------------
// Scratch (device globals; allocation-free rule)
// A-side operands carry hi+lo (exact split); B-side only hi (single rounding).
// ---------------------------------------------------------------------------
__device__ __half g_Xh[(size_t)ROWS * HID];
__device__ __half g_Xl[(size_t)ROWS * HID];
__device__ __half g_Wh[(size_t)3 * HID * HID];
__device__ __half g_Qh[(size_t)ROWS * HID];
__device__ __half g_Ql[(size_t)ROWS * HID];
__device__ __half g_Kh[(size_t)ROWS * HID];
__device__ float  g_V [(size_t)ROWS * HID];
__device__ __half g_Vth[(size_t)ROWS * HID]; // [b][h][s]
__device__ float  g_Sc[(size_t)NB * SEQ * SEQ];
__device__ __half g_Ph[(size_t)NB * SEQ * SEQ];
__device__ __half g_Pl[(size_t)NB * SEQ * SEQ];

// ---------------------------------------------------------------------------
// PTX helpers (sm_80-era: cp.async / ldmatrix / mma.sync — compile on sm_103)
// ---------------------------------------------------------------------------
__device__ __forceinline__ uint32_t smem_u32(const void* p) {
    uint32_t a;
    asm("{ .reg .u64 t; cvta.to.shared.u64 t, %1; cvt.u32.u64 %0, t; }"
        : "=r"(a) : "l"(p));
    return a;
}
__device__ __forceinline__ void cp_async16(uint32_t dst, const void* src) {
    asm volatile("cp.async.cg.shared.global [%0], [%1], 16;"
                 :: "r"(dst), "l"(src) : "memory");
}
#define CP_COMMIT()  asm volatile("cp.async.commit_group;" ::: "memory")
#define CP_WAIT(n)   asm volatile("cp.async.wait_group %0;" :: "n"(n) : "memory")

__device__ __forceinline__ void ldm_x4(uint32_t& r0, uint32_t& r1,
                                       uint32_t& r2, uint32_t& r3, uint32_t addr) {
    asm volatile("ldmatrix.sync.aligned.m8n8.x4.shared.b16 {%0,%1,%2,%3}, [%4];"
                 : "=r"(r0), "=r"(r1), "=r"(r2), "=r"(r3) : "r"(addr));
}
__device__ __forceinline__ void mma_f16(float& d0, float& d1, float& d2, float& d3,
                                        uint32_t a0, uint32_t a1, uint32_t a2, uint32_t a3,
                                        uint32_t b0, uint32_t b1) {
    asm volatile(
        "mma.sync.aligned.m16n8k16.row.col.f32.f16.f16.f32 "
        "{%0,%1,%2,%3}, {%4,%5,%6,%7}, {%8,%9}, {%0,%1,%2,%3};"
        : "+f"(d0), "+f"(d1), "+f"(d2), "+f"(d3)
        : "r"(a0), "r"(a1), "r"(a2), "r"(a3), "r"(b0), "r"(b1));
}

// ---------------------------------------------------------------------------
// SMEM tile layout: BK=64. 128 rows x 64 fp16 (128B data) with 144B row stride
// (16B pad): 144*r mod 128 = 16*r mod 128 distinct for 8 consecutive rows ->
// conflict-free ldmatrix. 3 matrices per stage (Ah, Al, Bh), 2 stages.
// ---------------------------------------------------------------------------
static constexpr int RS        = 144;                // bytes per row
static constexpr int MAT_BYTES = 128 * RS;           // 18432
static constexpr int STG_BYTES = 3 * MAT_BYTES;      // 55296
static constexpr int SMEM_BYTES = 2 * STG_BYTES;     // 110592 (x2 CTAs fits 228K)

__device__ __forceinline__ void stage_load(
    const __half* __restrict__ Ah, const __half* __restrict__ Al,
    const __half* __restrict__ Bh,
    int K, int k0, uint32_t sb, int tid)
{
#pragma unroll
    for (int i = 0; i < 4; i++) {
        const int chunk = tid + (i << 8);       // 0..1023
        const int row = chunk >> 3;
        const int cc  = chunk & 7;
        const size_t go = (size_t)row * K + k0 + (cc << 3);
        const uint32_t so = (uint32_t)(row * RS + (cc << 4));
        cp_async16(sb + so,                 Ah + go);
        cp_async16(sb + so + MAT_BYTES,     Al + go);
        cp_async16(sb + so + 2 * MAT_BYTES, Bh + go);
    }
}

// ---------------------------------------------------------------------------
// 2-pass fp16 GEMM NT: C = alpha*(Ahi+Alo)·Bh^T + bias  (B single-rounded fp16)
// A: [M,K] K-major hi/lo fp16; B: [N,K] K-major hi fp16.
// C!=null -> fp32 out; Ch -> fp16 hi out; Cl -> fp16 lo out (each optional).
// blockIdx.z batches. 2 CTAs/SM.
// ---------------------------------------------------------------------------
__global__ void __launch_bounds__(256, 2)
gemm2_mma_kernel(const __half* __restrict__ Ah, const __half* __restrict__ Al,
                 const __half* __restrict__ Bh,
                 const float* __restrict__ bias,
                 float* __restrict__ C, __half* __restrict__ Ch,
                 __half* __restrict__ Cl,
                 int N, int K, float alpha,
                 size_t sA, size_t sB, size_t sC)
{
    extern __shared__ char smem[];
    const uint32_t sbase = smem_u32(smem);
    const int tid = threadIdx.x;
    const int wid = tid >> 5;
    const int lid = tid & 31;
    const int wm  = wid >> 2;   // 0..1 : 64-row slab
    const int wn  = wid & 3;    // 0..3 : 32-col slab

    const size_t offA = (size_t)blockIdx.z * sA + (size_t)blockIdx.y * 128 * K;
    const size_t offB = (size_t)blockIdx.z * sB + (size_t)blockIdx.x * 128 * K;
    const size_t zC   = (size_t)blockIdx.z * sC;
    Ah += offA; Al += offA; Bh += offB;

    float acc[4][4][4];
#pragma unroll
    for (int mi = 0; mi < 4; mi++)
#pragma unroll
        for (int ni = 0; ni < 4; ni++)
#pragma unroll
            for (int r = 0; r < 4; r++) acc[mi][ni][r] = 0.0f;

    const int nch = K >> 6; // chunks of BK=64

    // Prefetch stages 0 and 1
    stage_load(Ah, Al, Bh, K, 0, sbase, tid);
    CP_COMMIT();
    stage_load(Ah, Al, Bh, K, 64, sbase + STG_BYTES, tid);
    CP_COMMIT();
    CP_WAIT(1);
    __syncthreads();

    // ldmatrix lane address components (within a 128x64 tile)
    const int a_row = wm * 64 + (((lid >> 3) & 1) << 3) + (lid & 7); // + mi*16
    const int a_chs = (lid >> 4) & 1;                                // + ks*2
    const int b_row = wn * 32 + (((lid >> 4) & 1) << 3) + (lid & 7); // + pr*16
    const int b_chs = (lid >> 3) & 1;                                // + ks*2

    for (int c = 0; c < nch; c++) {
        const uint32_t tb = sbase + (uint32_t)((c & 1) * STG_BYTES);
#pragma unroll
        for (int ks = 0; ks < 4; ks++) {
            uint32_t ah[4][4], al[4][4];
            const uint32_t acol = (uint32_t)(((ks << 1) + a_chs) << 4);
            const uint32_t bcol = (uint32_t)(((ks << 1) + b_chs) << 4);
#pragma unroll
            for (int mi = 0; mi < 4; mi++) {
                const uint32_t ad = tb + (uint32_t)((a_row + mi * 16) * RS) + acol;
                ldm_x4(ah[mi][0], ah[mi][1], ah[mi][2], ah[mi][3], ad);
                ldm_x4(al[mi][0], al[mi][1], al[mi][2], al[mi][3], ad + MAT_BYTES);
            }
#pragma unroll
            for (int pr = 0; pr < 2; pr++) {
                uint32_t bh[4];
                const uint32_t bd = tb + 2 * MAT_BYTES +
                                    (uint32_t)((b_row + pr * 16) * RS) + bcol;
                ldm_x4(bh[0], bh[1], bh[2], bh[3], bd);
#pragma unroll
                for (int mi = 0; mi < 4; mi++)
#pragma unroll
                    for (int q = 0; q < 2; q++) {
                        const int of = q << 1;
                        float* d = acc[mi][pr * 2 + q];
                        // hi pass
                        mma_f16(d[0], d[1], d[2], d[3],
                                ah[mi][0], ah[mi][1], ah[mi][2], ah[mi][3],
                                bh[of], bh[of + 1]);
                        // lo pass (A residual)
                        mma_f16(d[0], d[1], d[2], d[3],
                                al[mi][0], al[mi][1], al[mi][2], al[mi][3],
                                bh[of], bh[of + 1]);
                    }
            }
        }
        __syncthreads();           // all warps done reading this buffer
        if (c + 2 < nch) {
            stage_load(Ah, Al, Bh, K, (c + 2) << 6,
                       sbase + (uint32_t)((c & 1) * STG_BYTES), tid);
            CP_COMMIT();
            CP_WAIT(1);            // next buffer (c+1) ready
        } else {
            CP_WAIT(0);
        }
        __syncthreads();
    }

    // Epilogue: direct register -> global stores
    const int t4 = lid >> 2;         // 0..7  row within 8
    const int t2 = (lid & 3) << 1;   // col pair
#pragma unroll
    for (int ni = 0; ni < 4; ni++) {
        const int gcol = blockIdx.x * 128 + wn * 32 + ni * 8 + t2;
        float bi0 = 0.0f, bi1 = 0.0f;
        if (bias) { bi0 = bias[gcol]; bi1 = bias[gcol + 1]; }
#pragma unroll
        for (int mi = 0; mi < 4; mi++) {
            const int grow = blockIdx.y * 128 + wm * 64 + mi * 16 + t4;
            const float* d = acc[mi][ni];
            float v00 = fmaf(alpha, d[0], bi0);
            float v01 = fmaf(alpha, d[1], bi1);
            float v10 = fmaf(alpha, d[2], bi0);
            float v11 = fmaf(alpha, d[3], bi1);
            const size_t o0 = zC + (size_t)grow * N + gcol;
            const size_t o1 = o0 + (size_t)8 * N;
            if (C) {
                *reinterpret_cast<float2*>(C + o0) = make_float2(v00, v01);
                *reinterpret_cast<float2*>(C + o1) = make_float2(v10, v11);
            }
            __half h00, h01, h10, h11;
            if (Ch) {
                h00 = __float2half(v00); h01 = __float2half(v01);
                h10 = __float2half(v10); h11 = __float2half(v11);
                *reinterpret_cast<__half2*>(Ch + o0) = __halves2half2(h00, h01);
                *reinterpret_cast<__half2*>(Ch + o1) = __halves2half2(h10, h11);
            }
            if (Cl) {
                __half l00 = __float2half(v00 - __half2float(h00));
                __half l01 = __float2half(v01 - __half2float(h01));
                __half l10 = __float2half(v10 - __half2float(h10));
                __half l11 = __float2half(v11 - __half2float(h11));
                *reinterpret_cast<__half2*>(Cl + o0) = __halves2half2(l00, l01);
                *reinterpret_cast<__half2*>(Cl + o1) = __halves2half2(l10, l11);
            }
        }
    }
}

// ---------------------------------------------------------------------------
// fp32 -> fp16 hi (+ optional lo), vectorized by 4
// ---------------------------------------------------------------------------
__global__ void __launch_bounds__(256)
split_kernel(const float* __restrict__ x, __half* __restrict__ hi,
             __half* __restrict__ lo, int n4)
{
    int i = blockIdx.x * 256 + threadIdx.x;
    if (i >= n4) return;
    float4 v = reinterpret_cast<const float4*>(x)[i];
    __half h0 = __float2half(v.x), h1 = __float2half(v.y);
    __half h2 = __float2half(v.z), h3 = __float2half(v.w);
    reinterpret_cast<__half2*>(hi)[2 * i]     = __halves2half2(h0, h1);
    reinterpret_cast<__half2*>(hi)[2 * i + 1] = __halves2half2(h2, h3);
    if (lo) {
        __half l0 = __float2half(v.x - __half2float(h0));
        __half l1 = __float2half(v.y - __half2float(h1));
        __half l2 = __float2half(v.z - __half2float(h2));
        __half l3 = __float2half(v.w - __half2float(h3));
        reinterpret_cast<__half2*>(lo)[2 * i]     = __halves2half2(l0, l1);
        reinterpret_cast<__half2*>(lo)[2 * i + 1] = __halves2half2(l2, l3);
    }
}

// ---------------------------------------------------------------------------
// V [b][s][h] fp32 -> Vt hi [b][h][s] fp16 (transpose, single rounding)
// ---------------------------------------------------------------------------
__global__ void __launch_bounds__(256)
transpose_h_kernel(const float* __restrict__ V, __half* __restrict__ Th)
{
    __shared__ float tile[32][33];
    const int b = blockIdx.z;
    const int h0 = blockIdx.x * 32, s0 = blockIdx.y * 32;
    const int tx = threadIdx.x & 31, ty = threadIdx.x >> 5; // 32 x 8
    const float* Vb = V + (size_t)b * SEQ * HID;
#pragma unroll
    for (int j = 0; j < 32; j += 8)
        tile[ty + j][tx] = Vb[(size_t)(s0 + ty + j) * HID + h0 + tx];
    __syncthreads();
    __half* Thb = Th + (size_t)b * HID * SEQ;
#pragma unroll
    for (int j = 0; j < 32; j += 8) {
        float v = tile[tx][ty + j];
        Thb[(size_t)(h0 + ty + j) * SEQ + s0 + tx] = __float2half(v);
    }
}

// ---------------------------------------------------------------------------
// Row softmax (2048 cols) fused with fp16 hi/lo split of P
// ---------------------------------------------------------------------------
__global__ void __launch_bounds__(256)
softmax_split_kernel(const float* __restrict__ Sc,
                     __half* __restrict__ Ph, __half* __restrict__ Pl)
{
    __shared__ float red[256];
    const float* row = Sc + (size_t)blockIdx.x * SEQ;
    const int tid = threadIdx.x;

    float4 v0 = reinterpret_cast<const float4*>(row)[tid];
    float4 v1 = reinterpret_cast<const float4*>(row)[tid + 256];

    float m = fmaxf(fmaxf(fmaxf(v0.x, v0.y), fmaxf(v0.z, v0.w)),
                    fmaxf(fmaxf(v1.x, v1.y), fmaxf(v1.z, v1.w)));
    red[tid] = m;
    __syncthreads();
#pragma unroll
    for (int s = 128; s > 0; s >>= 1) {
        if (tid < s) red[tid] = fmaxf(red[tid], red[tid + s]);
        __syncthreads();
    }
    m = red[0];
    __syncthreads();

    v0.x = __expf(v0.x - m); v0.y = __expf(v0.y - m);
    v0.z = __expf(v0.z - m); v0.w = __expf(v0.w - m);
    v1.x = __expf(v1.x - m); v1.y = __expf(v1.y - m);
    v1.z = __expf(v1.z - m); v1.w = __expf(v1.w - m);

    red[tid] = v0.x + v0.y + v0.z + v0.w + v1.x + v1.y + v1.z + v1.w;
    __syncthreads();
#pragma unroll
    for (int s = 128; s > 0; s >>= 1) {
        if (tid < s) red[tid] += red[tid + s];
        __syncthreads();
    }
    const float inv = 1.0f / red[0];

    const size_t ro = (size_t)blockIdx.x * SEQ;
    __half2* H = reinterpret_cast<__half2*>(Ph + ro);
    __half2* L = reinterpret_cast<__half2*>(Pl + ro);
    float p[8] = {v0.x * inv, v0.y * inv, v0.z * inv, v0.w * inv,
                  v1.x * inv, v1.y * inv, v1.z * inv, v1.w * inv};
    __half hh[8], ll[8];
#pragma unroll
    for (int j = 0; j < 8; j++) {
        hh[j] = __float2half(p[j]);
        ll[j] = __float2half(p[j] - __half2float(hh[j]));
    }
    H[2 * tid]           = __halves2half2(hh[0], hh[1]);
    H[2 * tid + 1]       = __halves2half2(hh[2], hh[3]);
    H[512 + 2 * tid]     = __halves2half2(hh[4], hh[5]);
    H[512 + 2 * tid + 1] = __halves2half2(hh[6], hh[7]);
    L[2 * tid]           = __halves2half2(ll[0], ll[1]);
    L[2 * tid + 1]       = __halves2half2(ll[2], ll[3]);
    L[512 + 2 * tid]     = __halves2half2(ll[4], ll[5]);
    L[512 + 2 * tid + 1] = __halves2half2(ll[6], ll[7]);
}

// ---------------------------------------------------------------------------
// Launch
// ---------------------------------------------------------------------------
extern "C" void kernel_launch(void* const* d_in, const int* in_sizes, int n_in,
                              void* d_out, int out_size)
{
    const float* X  = (const float*)d_in[0];
    const float* Wq = (const float*)d_in[1];
    const float* bq = (const float*)d_in[2];
    const float* Wk = (const float*)d_in[3];
    const float* bk = (const float*)d_in[4];
    const float* Wv = (const float*)d_in[5];
    const float* bv = (const float*)d_in[6];
    float* out = (float*)d_out;

    __half *Xh, *Xl, *Wh, *Qh, *Ql, *Kh, *Vth, *Ph, *Pl;
    float *V, *Sc;
    cudaGetSymbolAddress((void**)&Xh, g_Xh);   cudaGetSymbolAddress((void**)&Xl, g_Xl);
    cudaGetSymbolAddress((void**)&Wh, g_Wh);
    cudaGetSymbolAddress((void**)&Qh, g_Qh);   cudaGetSymbolAddress((void**)&Ql, g_Ql);
    cudaGetSymbolAddress((void**)&Kh, g_Kh);
    cudaGetSymbolAddress((void**)&V,  g_V);
    cudaGetSymbolAddress((void**)&Vth, g_Vth);
    cudaGetSymbolAddress((void**)&Sc, g_Sc);
    cudaGetSymbolAddress((void**)&Ph, g_Ph);   cudaGetSymbolAddress((void**)&Pl, g_Pl);

    cudaFuncSetAttribute(gemm2_mma_kernel,
                         cudaFuncAttributeMaxDynamicSharedMemorySize, SMEM_BYTES);

    // Split inputs: X -> hi+lo (A side); W -> hi only (B side)
    {
        int n4 = ROWS * HID / 4;
        split_kernel<<<(n4 + 255) / 256, 256>>>(X, Xh, Xl, n4);
        int w4 = HID * HID / 4;
        split_kernel<<<(w4 + 255) / 256, 256>>>(Wq, Wh, nullptr, w4);
        split_kernel<<<(w4 + 255) / 256, 256>>>(Wk, Wh + (size_t)HID * HID, nullptr, w4);
        split_kernel<<<(w4 + 255) / 256, 256>>>(Wv, Wh + (size_t)2 * HID * HID, nullptr, w4);
    }

    dim3 blk(256);

    // QKV projections: [8192,1024] = X @ W^T + b
    dim3 gq(HID / 128, ROWS / 128, 1);
    gemm2_mma_kernel<<<gq, blk, SMEM_BYTES>>>(Xh, Xl, Wh, bq,
                                              nullptr, Qh, Ql,
                                              HID, HID, 1.0f, 0, 0, 0);
    gemm2_mma_kernel<<<gq, blk, SMEM_BYTES>>>(Xh, Xl, Wh + (size_t)HID * HID, bk,
                                              nullptr, Kh, nullptr,
                                              HID, HID, 1.0f, 0, 0, 0);
    gemm2_mma_kernel<<<gq, blk, SMEM_BYTES>>>(Xh, Xl, Wh + (size_t)2 * HID * HID, bv,
                                              V, nullptr, nullptr,
                                              HID, HID, 1.0f, 0, 0, 0);

    // V -> Vt hi (per batch: [h][s])
    {
        dim3 gt(HID / 32, SEQ / 32, NB);
        transpose_h_kernel<<<gt, 256>>>(V, Vth);
    }

    // scores[b] = Q[b] @ K[b]^T / 32
    dim3 gs(SEQ / 128, SEQ / 128, NB);
    gemm2_mma_kernel<<<gs, blk, SMEM_BYTES>>>(Qh, Ql, Kh, nullptr,
                                              Sc, nullptr, nullptr,
                                              SEQ, HID, 0.03125f,
                                              (size_t)SEQ * HID, (size_t)SEQ * HID,
                                              (size_t)SEQ * SEQ);

    // softmax + split P
    softmax_split_kernel<<<NB * SEQ, 256>>>(Sc, Ph, Pl);

    // out[b] = P[b] @ Vt[b]^T  (Vt is [N=hid, K=seq] K-major)
    dim3 ga(HID / 128, SEQ / 128, NB);
    gemm2_mma_kernel<<<ga, blk, SMEM_BYTES>>>(Ph, Pl, Vth, nullptr,
                                              out, nullptr, nullptr,
                                              HID, SEQ, 1.0f,
                                              (size_t)SEQ * SEQ, (size_t)SEQ * HID,
                                              (size_t)SEQ * HID);
}

// round 14
// speedup vs baseline: 1.4960x; 1.4960x over previous
#include <cuda_runtime.h>
#include <cuda_fp16.h>
#include <cstdint>

// Problem constants
static constexpr int HID  = 1024;
static constexpr int NB   = 4;
static constexpr int SEQ  = 2048;
static constexpr int ROWS = NB * SEQ; // 8192

// ---------------------------------------------------------------------------
// Scratch (device globals; allocation-free rule)
// A-side operands carry hi+lo (exact split); B-side only hi (single rounding).
// ---------------------------------------------------------------------------
__device__ __half g_Xh[(size_t)ROWS * HID];
__device__ __half g_Xl[(size_t)ROWS * HID];
__device__ __half g_Wh[(size_t)3 * HID * HID];
__device__ __half g_Qh[(size_t)ROWS * HID];
__device__ __half g_Ql[(size_t)ROWS * HID];
__device__ __half g_Kh[(size_t)ROWS * HID];
__device__ float  g_V [(size_t)ROWS * HID];
__device__ __half g_Vth[(size_t)ROWS * HID]; // [b][h][s]
__device__ float  g_Sc[(size_t)NB * SEQ * SEQ];
__device__ __half g_Ph[(size_t)NB * SEQ * SEQ];
__device__ __half g_Pl[(size_t)NB * SEQ * SEQ];

// ---------------------------------------------------------------------------
// PTX helpers
// ---------------------------------------------------------------------------
__device__ __forceinline__ uint32_t smem_u32(const void* p) {
    uint32_t a;
    asm("{ .reg .u64 t; cvta.to.shared.u64 t, %1; cvt.u32.u64 %0, t; }"
        : "=r"(a) : "l"(p));
    return a;
}
__device__ __forceinline__ void cp_async16(uint32_t dst, const void* src) {
    asm volatile("cp.async.cg.shared.global [%0], [%1], 16;"
                 :: "r"(dst), "l"(src) : "memory");
}
#define CP_COMMIT()  asm volatile("cp.async.commit_group;" ::: "memory")
#define CP_WAIT(n)   asm volatile("cp.async.wait_group %0;" :: "n"(n) : "memory")

__device__ __forceinline__ void ldm_x4(uint32_t& r0, uint32_t& r1,
                                       uint32_t& r2, uint32_t& r3, uint32_t addr) {
    asm volatile("ldmatrix.sync.aligned.m8n8.x4.shared.b16 {%0,%1,%2,%3}, [%4];"
                 : "=r"(r0), "=r"(r1), "=r"(r2), "=r"(r3) : "r"(addr));
}
__device__ __forceinline__ void mma_f16(float& d0, float& d1, float& d2, float& d3,
                                        uint32_t a0, uint32_t a1, uint32_t a2, uint32_t a3,
                                        uint32_t b0, uint32_t b1) {
    asm volatile(
        "mma.sync.aligned.m16n8k16.row.col.f32.f16.f16.f32 "
        "{%0,%1,%2,%3}, {%4,%5,%6,%7}, {%8,%9}, {%0,%1,%2,%3};"
        : "+f"(d0), "+f"(d1), "+f"(d2), "+f"(d3)
        : "r"(a0), "r"(a1), "r"(a2), "r"(a3), "r"(b0), "r"(b1));
}

// ---------------------------------------------------------------------------
// Tile config: BM=128, BN=256, BK=64, 3 stages, 512 threads (16 warps, 4x4).
// Rows padded to 144B: 16*r mod 128 distinct for 8 consecutive rows ->
// conflict-free ldmatrix. Per stage: Ah[128x64], Al[128x64], Bh[256x64].
// ---------------------------------------------------------------------------
static constexpr int RS       = 144;
static constexpr int MATA     = 128 * RS;            // 18432
static constexpr int B_OFF    = 2 * MATA;            // 36864
static constexpr int STG_BYTES = 2 * MATA + 256 * RS; // 73728
static constexpr int SMEM_BYTES = 3 * STG_BYTES;     // 221184

__device__ __forceinline__ void stage_load(
    const __half* __restrict__ Ah, const __half* __restrict__ Al,
    const __half* __restrict__ Bh,
    int K, int k0, uint32_t sb, int tid)
{
    // 4096 16B vectors / 512 threads = 8 each. i=0,1 -> Ah; 2,3 -> Al; 4..7 -> Bh
#pragma unroll
    for (int i = 0; i < 2; i++) {
        const int v = tid + (i << 9);           // 0..1023
        const int r = v >> 3, c = v & 7;
        cp_async16(sb + (uint32_t)(r * RS + (c << 4)),
                   Ah + (size_t)r * K + k0 + (c << 3));
    }
#pragma unroll
    for (int i = 0; i < 2; i++) {
        const int v = tid + (i << 9);
        const int r = v >> 3, c = v & 7;
        cp_async16(sb + (uint32_t)(MATA + r * RS + (c << 4)),
                   Al + (size_t)r * K + k0 + (c << 3));
    }
#pragma unroll
    for (int i = 0; i < 4; i++) {
        const int v = tid + (i << 9);           // 0..2047
        const int r = v >> 3, c = v & 7;
        cp_async16(sb + (uint32_t)(B_OFF + r * RS + (c << 4)),
                   Bh + (size_t)r * K + k0 + (c << 3));
    }
}

// ---------------------------------------------------------------------------
// 2-pass fp16 GEMM NT: C = alpha*(Ahi+Alo)·Bh^T + bias  (B single-rounded fp16)
// A: [M,K] K-major hi/lo fp16; B: [N,K] K-major hi fp16.
// 128x256 tile, 3-stage pipeline, one __syncthreads per chunk.
// ---------------------------------------------------------------------------
__global__ void __launch_bounds__(512, 1)
gemm2_mma_kernel(const __half* __restrict__ Ah, const __half* __restrict__ Al,
                 const __half* __restrict__ Bh,
                 const float* __restrict__ bias,
                 float* __restrict__ C, __half* __restrict__ Ch,
                 __half* __restrict__ Cl,
                 int N, int K, float alpha,
                 size_t sA, size_t sB, size_t sC)
{
    extern __shared__ char smem[];
    const uint32_t sbase = smem_u32(smem);
    const int tid = threadIdx.x;
    const int wid = tid >> 5;
    const int lid = tid & 31;
    const int wm  = wid >> 2;   // 0..3 : 32-row slab
    const int wn  = wid & 3;    // 0..3 : 64-col slab

    const size_t offA = (size_t)blockIdx.z * sA + (size_t)blockIdx.y * 128 * K;
    const size_t offB = (size_t)blockIdx.z * sB + (size_t)blockIdx.x * 256 * K;
    const size_t zC   = (size_t)blockIdx.z * sC;
    Ah += offA; Al += offA; Bh += offB;

    float acc[2][8][4];
#pragma unroll
    for (int mi = 0; mi < 2; mi++)
#pragma unroll
        for (int ni = 0; ni < 8; ni++)
#pragma unroll
            for (int r = 0; r < 4; r++) acc[mi][ni][r] = 0.0f;

    const int nch = K >> 6; // chunks of BK=64

    // Prefetch STAGES-1 = 2 stages
    stage_load(Ah, Al, Bh, K, 0, sbase, tid);
    CP_COMMIT();
    stage_load(Ah, Al, Bh, K, 64, sbase + STG_BYTES, tid);
    CP_COMMIT();

    // ldmatrix lane address components
    const int a_row = wm * 32 + (((lid >> 3) & 1) << 3) + (lid & 7); // + mi*16
    const int a_chs = (lid >> 4) & 1;                                // + ks*2
    const int b_row = wn * 64 + (((lid >> 4) & 1) << 3) + (lid & 7); // + pr*16
    const int b_chs = (lid >> 3) & 1;                                // + ks*2

    int slot = 0;
    for (int c = 0; c < nch; c++) {
        if (c == nch - 1) { CP_WAIT(0); } else { CP_WAIT(1); }
        __syncthreads();   // stage c visible to all; all warps past stage c-1

        // Issue loads for chunk c+2 into the slot freed by chunk c-1
        if (c + 2 < nch) {
            const int wslot = (slot + 2 >= 3) ? (slot - 1) : (slot + 2);
            stage_load(Ah, Al, Bh, K, (c + 2) << 6,
                       sbase + (uint32_t)(wslot * STG_BYTES), tid);
            CP_COMMIT();
        }

        const uint32_t tb = sbase + (uint32_t)(slot * STG_BYTES);
#pragma unroll
        for (int ks = 0; ks < 4; ks++) {
            uint32_t ah[2][4], al[2][4];
            const uint32_t acol = (uint32_t)(((ks << 1) + a_chs) << 4);
            const uint32_t bcol = (uint32_t)(((ks << 1) + b_chs) << 4);
#pragma unroll
            for (int mi = 0; mi < 2; mi++) {
                const uint32_t ad = tb + (uint32_t)((a_row + mi * 16) * RS) + acol;
                ldm_x4(ah[mi][0], ah[mi][1], ah[mi][2], ah[mi][3], ad);
                ldm_x4(al[mi][0], al[mi][1], al[mi][2], al[mi][3], ad + MATA);
            }
#pragma unroll
            for (int pr = 0; pr < 4; pr++) {
                uint32_t bh[4];
                const uint32_t bd = tb + (uint32_t)(B_OFF + (b_row + pr * 16) * RS) + bcol;
                ldm_x4(bh[0], bh[1], bh[2], bh[3], bd);
#pragma unroll
                for (int mi = 0; mi < 2; mi++)
#pragma unroll
                    for (int q = 0; q < 2; q++) {
                        const int of = q << 1;
                        float* d = acc[mi][pr * 2 + q];
                        mma_f16(d[0], d[1], d[2], d[3],
                                ah[mi][0], ah[mi][1], ah[mi][2], ah[mi][3],
                                bh[of], bh[of + 1]);
                        mma_f16(d[0], d[1], d[2], d[3],
                                al[mi][0], al[mi][1], al[mi][2], al[mi][3],
                                bh[of], bh[of + 1]);
                    }
            }
        }
        slot = (slot == 2) ? 0 : (slot + 1);
    }

    // Epilogue: direct register -> global stores
    const int t4 = lid >> 2;         // 0..7  row within 8
    const int t2 = (lid & 3) << 1;   // col pair
#pragma unroll
    for (int ni = 0; ni < 8; ni++) {
        const int gcol = blockIdx.x * 256 + wn * 64 + ni * 8 + t2;
        float bi0 = 0.0f, bi1 = 0.0f;
        if (bias) { bi0 = bias[gcol]; bi1 = bias[gcol + 1]; }
#pragma unroll
        for (int mi = 0; mi < 2; mi++) {
            const int grow = blockIdx.y * 128 + wm * 32 + mi * 16 + t4;
            const float* d = acc[mi][ni];
            float v00 = fmaf(alpha, d[0], bi0);
            float v01 = fmaf(alpha, d[1], bi1);
            float v10 = fmaf(alpha, d[2], bi0);
            float v11 = fmaf(alpha, d[3], bi1);
            const size_t o0 = zC + (size_t)grow * N + gcol;
            const size_t o1 = o0 + (size_t)8 * N;
            if (C) {
                *reinterpret_cast<float2*>(C + o0) = make_float2(v00, v01);
                *reinterpret_cast<float2*>(C + o1) = make_float2(v10, v11);
            }
            __half h00, h01, h10, h11;
            if (Ch) {
                h00 = __float2half(v00); h01 = __float2half(v01);
                h10 = __float2half(v10); h11 = __float2half(v11);
                *reinterpret_cast<__half2*>(Ch + o0) = __halves2half2(h00, h01);
                *reinterpret_cast<__half2*>(Ch + o1) = __halves2half2(h10, h11);
            }
            if (Cl) {
                __half l00 = __float2half(v00 - __half2float(h00));
                __half l01 = __float2half(v01 - __half2float(h01));
                __half l10 = __float2half(v10 - __half2float(h10));
                __half l11 = __float2half(v11 - __half2float(h11));
                *reinterpret_cast<__half2*>(Cl + o0) = __halves2half2(l00, l01);
                *reinterpret_cast<__half2*>(Cl + o1) = __halves2half2(l10, l11);
            }
        }
    }
}

// ---------------------------------------------------------------------------
// fp32 -> fp16 hi (+ optional lo), vectorized by 4
// ---------------------------------------------------------------------------
__global__ void __launch_bounds__(256)
split_kernel(const float* __restrict__ x, __half* __restrict__ hi,
             __half* __restrict__ lo, int n4)
{
    int i = blockIdx.x * 256 + threadIdx.x;
    if (i >= n4) return;
    float4 v = reinterpret_cast<const float4*>(x)[i];
    __half h0 = __float2half(v.x), h1 = __float2half(v.y);
    __half h2 = __float2half(v.z), h3 = __float2half(v.w);
    reinterpret_cast<__half2*>(hi)[2 * i]     = __halves2half2(h0, h1);
    reinterpret_cast<__half2*>(hi)[2 * i + 1] = __halves2half2(h2, h3);
    if (lo) {
        __half l0 = __float2half(v.x - __half2float(h0));
        __half l1 = __float2half(v.y - __half2float(h1));
        __half l2 = __float2half(v.z - __half2float(h2));
        __half l3 = __float2half(v.w - __half2float(h3));
        reinterpret_cast<__half2*>(lo)[2 * i]     = __halves2half2(l0, l1);
        reinterpret_cast<__half2*>(lo)[2 * i + 1] = __halves2half2(l2, l3);
    }
}

// ---------------------------------------------------------------------------
// V [b][s][h] fp32 -> Vt hi [b][h][s] fp16 (transpose, single rounding)
// ---------------------------------------------------------------------------
__global__ void __launch_bounds__(256)
transpose_h_kernel(const float* __restrict__ V, __half* __restrict__ Th)
{
    __shared__ float tile[32][33];
    const int b = blockIdx.z;
    const int h0 = blockIdx.x * 32, s0 = blockIdx.y * 32;
    const int tx = threadIdx.x & 31, ty = threadIdx.x >> 5; // 32 x 8
    const float* Vb = V + (size_t)b * SEQ * HID;
#pragma unroll
    for (int j = 0; j < 32; j += 8)
        tile[ty + j][tx] = Vb[(size_t)(s0 + ty + j) * HID + h0 + tx];
    __syncthreads();
    __half* Thb = Th + (size_t)b * HID * SEQ;
#pragma unroll
    for (int j = 0; j < 32; j += 8) {
        float v = tile[tx][ty + j];
        Thb[(size_t)(h0 + ty + j) * SEQ + s0 + tx] = __float2half(v);
    }
}

// ---------------------------------------------------------------------------
// Row softmax (2048 cols) fused with fp16 hi/lo split of P
// ---------------------------------------------------------------------------
__global__ void __launch_bounds__(256)
softmax_split_kernel(const float* __restrict__ Sc,
                     __half* __restrict__ Ph, __half* __restrict__ Pl)
{
    __shared__ float red[256];
    const float* row = Sc + (size_t)blockIdx.x * SEQ;
    const int tid = threadIdx.x;

    float4 v0 = reinterpret_cast<const float4*>(row)[tid];
    float4 v1 = reinterpret_cast<const float4*>(row)[tid + 256];

    float m = fmaxf(fmaxf(fmaxf(v0.x, v0.y), fmaxf(v0.z, v0.w)),
                    fmaxf(fmaxf(v1.x, v1.y), fmaxf(v1.z, v1.w)));
    red[tid] = m;
    __syncthreads();
#pragma unroll
    for (int s = 128; s > 0; s >>= 1) {
        if (tid < s) red[tid] = fmaxf(red[tid], red[tid + s]);
        __syncthreads();
    }
    m = red[0];
    __syncthreads();

    v0.x = __expf(v0.x - m); v0.y = __expf(v0.y - m);
    v0.z = __expf(v0.z - m); v0.w = __expf(v0.w - m);
    v1.x = __expf(v1.x - m); v1.y = __expf(v1.y - m);
    v1.z = __expf(v1.z - m); v1.w = __expf(v1.w - m);

    red[tid] = v0.x + v0.y + v0.z + v0.w + v1.x + v1.y + v1.z + v1.w;
    __syncthreads();
#pragma unroll
    for (int s = 128; s > 0; s >>= 1) {
        if (tid < s) red[tid] += red[tid + s];
        __syncthreads();
    }
    const float inv = 1.0f / red[0];

    const size_t ro = (size_t)blockIdx.x * SEQ;
    __half2* H = reinterpret_cast<__half2*>(Ph + ro);
    __half2* L = reinterpret_cast<__half2*>(Pl + ro);
    float p[8] = {v0.x * inv, v0.y * inv, v0.z * inv, v0.w * inv,
                  v1.x * inv, v1.y * inv, v1.z * inv, v1.w * inv};
    __half hh[8], ll[8];
#pragma unroll
    for (int j = 0; j < 8; j++) {
        hh[j] = __float2half(p[j]);
        ll[j] = __float2half(p[j] - __half2float(hh[j]));
    }
    H[2 * tid]           = __halves2half2(hh[0], hh[1]);
    H[2 * tid + 1]       = __halves2half2(hh[2], hh[3]);
    H[512 + 2 * tid]     = __halves2half2(hh[4], hh[5]);
    H[512 + 2 * tid + 1] = __halves2half2(hh[6], hh[7]);
    L[2 * tid]           = __halves2half2(ll[0], ll[1]);
    L[2 * tid + 1]       = __halves2half2(ll[2], ll[3]);
    L[512 + 2 * tid]     = __halves2half2(ll[4], ll[5]);
    L[512 + 2 * tid + 1] = __halves2half2(ll[6], ll[7]);
}

// ---------------------------------------------------------------------------
// Launch
// ---------------------------------------------------------------------------
extern "C" void kernel_launch(void* const* d_in, const int* in_sizes, int n_in,
                              void* d_out, int out_size)
{
    const float* X  = (const float*)d_in[0];
    const float* Wq = (const float*)d_in[1];
    const float* bq = (const float*)d_in[2];
    const float* Wk = (const float*)d_in[3];
    const float* bk = (const float*)d_in[4];
    const float* Wv = (const float*)d_in[5];
    const float* bv = (const float*)d_in[6];
    float* out = (float*)d_out;

    __half *Xh, *Xl, *Wh, *Qh, *Ql, *Kh, *Vth, *Ph, *Pl;
    float *V, *Sc;
    cudaGetSymbolAddress((void**)&Xh, g_Xh);   cudaGetSymbolAddress((void**)&Xl, g_Xl);
    cudaGetSymbolAddress((void**)&Wh, g_Wh);
    cudaGetSymbolAddress((void**)&Qh, g_Qh);   cudaGetSymbolAddress((void**)&Ql, g_Ql);
    cudaGetSymbolAddress((void**)&Kh, g_Kh);
    cudaGetSymbolAddress((void**)&V,  g_V);
    cudaGetSymbolAddress((void**)&Vth, g_Vth);
    cudaGetSymbolAddress((void**)&Sc, g_Sc);
    cudaGetSymbolAddress((void**)&Ph, g_Ph);   cudaGetSymbolAddress((void**)&Pl, g_Pl);

    cudaFuncSetAttribute(gemm2_mma_kernel,
                         cudaFuncAttributeMaxDynamicSharedMemorySize, SMEM_BYTES);

    // Split inputs: X -> hi+lo (A side); W -> hi only (B side)
    {
        int n4 = ROWS * HID / 4;
        split_kernel<<<(n4 + 255) / 256, 256>>>(X, Xh, Xl, n4);
        int w4 = HID * HID / 4;
        split_kernel<<<(w4 + 255) / 256, 256>>>(Wq, Wh, nullptr, w4);
        split_kernel<<<(w4 + 255) / 256, 256>>>(Wk, Wh + (size_t)HID * HID, nullptr, w4);
        split_kernel<<<(w4 + 255) / 256, 256>>>(Wv, Wh + (size_t)2 * HID * HID, nullptr, w4);
    }

    dim3 blk(512);

    // QKV projections: [8192,1024] = X @ W^T + b
    dim3 gq(HID / 256, ROWS / 128, 1);
    gemm2_mma_kernel<<<gq, blk, SMEM_BYTES>>>(Xh, Xl, Wh, bq,
                                              nullptr, Qh, Ql,
                                              HID, HID, 1.0f, 0, 0, 0);
    gemm2_mma_kernel<<<gq, blk, SMEM_BYTES>>>(Xh, Xl, Wh + (size_t)HID * HID, bk,
                                              nullptr, Kh, nullptr,
                                              HID, HID, 1.0f, 0, 0, 0);
    gemm2_mma_kernel<<<gq, blk, SMEM_BYTES>>>(Xh, Xl, Wh + (size_t)2 * HID * HID, bv,
                                              V, nullptr, nullptr,
                                              HID, HID, 1.0f, 0, 0, 0);

    // V -> Vt hi (per batch: [h][s])
    {
        dim3 gt(HID / 32, SEQ / 32, NB);
        transpose_h_kernel<<<gt, 256>>>(V, Vth);
    }

    // scores[b] = Q[b] @ K[b]^T / 32
    dim3 gs(SEQ / 256, SEQ / 128, NB);
    gemm2_mma_kernel<<<gs, blk, SMEM_BYTES>>>(Qh, Ql, Kh, nullptr,
                                              Sc, nullptr, nullptr,
                                              SEQ, HID, 0.03125f,
                                              (size_t)SEQ * HID, (size_t)SEQ * HID,
                                              (size_t)SEQ * SEQ);

    // softmax + split P
    softmax_split_kernel<<<NB * SEQ, 256>>>(Sc, Ph, Pl);

    // out[b] = P[b] @ Vt[b]^T  (Vt is [N=hid, K=seq] K-major)
    dim3 ga(HID / 256, SEQ / 128, NB);
    gemm2_mma_kernel<<<ga, blk, SMEM_BYTES>>>(Ph, Pl, Vth, nullptr,
                                              out, nullptr, nullptr,
                                              HID, SEQ, 1.0f,
                                              (size_t)SEQ * SEQ, (size_t)SEQ * HID,
                                              (size_t)SEQ * HID);
}

// round 15
// speedup vs baseline: 2.5197x; 1.6843x over previous
#include <cuda_runtime.h>
#include <cuda_fp16.h>
#include <cstdint>

// Problem constants
static constexpr int HID  = 1024;
static constexpr int NB   = 4;
static constexpr int SEQ  = 2048;
static constexpr int ROWS = NB * SEQ; // 8192

// ---------------------------------------------------------------------------
// Scratch (device globals; allocation-free rule). All operands single-rounded
// fp16 (1-pass); fp32 kept only for scores (softmax needs it) and V staging.
// ---------------------------------------------------------------------------
__device__ __half g_Xh[(size_t)ROWS * HID];
__device__ __half g_Wh[(size_t)3 * HID * HID];
__device__ __half g_Qh[(size_t)ROWS * HID];
__device__ __half g_Kh[(size_t)ROWS * HID];
__device__ float  g_V [(size_t)ROWS * HID];
__device__ __half g_Vth[(size_t)ROWS * HID]; // [b][h][s]
__device__ float  g_Sc[(size_t)NB * SEQ * SEQ];
__device__ __half g_Ph[(size_t)NB * SEQ * SEQ];

// ---------------------------------------------------------------------------
// PTX helpers
// ---------------------------------------------------------------------------
__device__ __forceinline__ uint32_t smem_u32(const void* p) {
    uint32_t a;
    asm("{ .reg .u64 t; cvta.to.shared.u64 t, %1; cvt.u32.u64 %0, t; }"
        : "=r"(a) : "l"(p));
    return a;
}
__device__ __forceinline__ void cp_async16(uint32_t dst, const void* src) {
    asm volatile("cp.async.cg.shared.global [%0], [%1], 16;"
                 :: "r"(dst), "l"(src) : "memory");
}
#define CP_COMMIT()  asm volatile("cp.async.commit_group;" ::: "memory")
#define CP_WAIT(n)   asm volatile("cp.async.wait_group %0;" :: "n"(n) : "memory")

__device__ __forceinline__ void ldm_x4(uint32_t& r0, uint32_t& r1,
                                       uint32_t& r2, uint32_t& r3, uint32_t addr) {
    asm volatile("ldmatrix.sync.aligned.m8n8.x4.shared.b16 {%0,%1,%2,%3}, [%4];"
                 : "=r"(r0), "=r"(r1), "=r"(r2), "=r"(r3) : "r"(addr));
}
__device__ __forceinline__ void mma_f16(float& d0, float& d1, float& d2, float& d3,
                                        uint32_t a0, uint32_t a1, uint32_t a2, uint32_t a3,
                                        uint32_t b0, uint32_t b1) {
    asm volatile(
        "mma.sync.aligned.m16n8k16.row.col.f32.f16.f16.f32 "
        "{%0,%1,%2,%3}, {%4,%5,%6,%7}, {%8,%9}, {%0,%1,%2,%3};"
        : "+f"(d0), "+f"(d1), "+f"(d2), "+f"(d3)
        : "r"(a0), "r"(a1), "r"(a2), "r"(a3), "r"(b0), "r"(b1));
}

// ---------------------------------------------------------------------------
// Tile config: BM=128, BN=256, BK=64, 4 stages, 512 threads (16 warps, 4x4).
// Rows padded to 144B: 16*r mod 128 distinct for 8 consecutive rows ->
// conflict-free ldmatrix. Per stage: A[128x64] + B[256x64] fp16.
// ---------------------------------------------------------------------------
static constexpr int RS        = 144;
static constexpr int B_OFF     = 128 * RS;            // 18432
static constexpr int STG_BYTES = B_OFF + 256 * RS;    // 55296
static constexpr int SMEM_BYTES = 4 * STG_BYTES;      // 221184

__device__ __forceinline__ void stage_load(
    const __half* __restrict__ Ah, const __half* __restrict__ Bh,
    int K, int k0, uint32_t sb, int tid)
{
    // A: 1024 16B vectors, B: 2048. 512 threads -> 6 vectors each.
#pragma unroll
    for (int i = 0; i < 2; i++) {
        const int v = tid + (i << 9);
        const int r = v >> 3, c = v & 7;
        cp_async16(sb + (uint32_t)(r * RS + (c << 4)),
                   Ah + (size_t)r * K + k0 + (c << 3));
    }
#pragma unroll
    for (int i = 0; i < 4; i++) {
        const int v = tid + (i << 9);
        const int r = v >> 3, c = v & 7;
        cp_async16(sb + (uint32_t)(B_OFF + r * RS + (c << 4)),
                   Bh + (size_t)r * K + k0 + (c << 3));
    }
}

// ---------------------------------------------------------------------------
// Single-pass fp16 GEMM NT: C = alpha * A·B^T + bias
// A: [M,K] K-major fp16; B: [N,K] K-major fp16.
// C!=null -> fp32 out; Ch!=null -> fp16 out. blockIdx.z batches.
// 128x256 tile, 4-stage cp.async pipeline, one __syncthreads per chunk.
// ---------------------------------------------------------------------------
__global__ void __launch_bounds__(512, 1)
gemm1_mma_kernel(const __half* __restrict__ Ah, const __half* __restrict__ Bh,
                 const float* __restrict__ bias,
                 float* __restrict__ C, __half* __restrict__ Ch,
                 int N, int K, float alpha,
                 size_t sA, size_t sB, size_t sC)
{
    extern __shared__ char smem[];
    const uint32_t sbase = smem_u32(smem);
    const int tid = threadIdx.x;
    const int wid = tid >> 5;
    const int lid = tid & 31;
    const int wm  = wid >> 2;   // 0..3 : 32-row slab
    const int wn  = wid & 3;    // 0..3 : 64-col slab

    const size_t offA = (size_t)blockIdx.z * sA + (size_t)blockIdx.y * 128 * K;
    const size_t offB = (size_t)blockIdx.z * sB + (size_t)blockIdx.x * 256 * K;
    const size_t zC   = (size_t)blockIdx.z * sC;
    Ah += offA; Bh += offB;

    float acc[2][8][4];
#pragma unroll
    for (int mi = 0; mi < 2; mi++)
#pragma unroll
        for (int ni = 0; ni < 8; ni++)
#pragma unroll
            for (int r = 0; r < 4; r++) acc[mi][ni][r] = 0.0f;

    const int nch = K >> 6; // chunks of BK=64

    // Prefetch 3 of 4 stages
    stage_load(Ah, Bh, K, 0, sbase, tid);
    CP_COMMIT();
    stage_load(Ah, Bh, K, 64, sbase + STG_BYTES, tid);
    CP_COMMIT();
    stage_load(Ah, Bh, K, 128, sbase + 2 * STG_BYTES, tid);
    CP_COMMIT();

    // ldmatrix lane address components
    const int a_row = wm * 32 + (((lid >> 3) & 1) << 3) + (lid & 7); // + mi*16
    const int a_chs = (lid >> 4) & 1;                                // + ks*2
    const int b_row = wn * 64 + (((lid >> 4) & 1) << 3) + (lid & 7); // + pr*16
    const int b_chs = (lid >> 3) & 1;                                // + ks*2

    for (int c = 0; c < nch; c++) {
        CP_WAIT(2);        // with one commit per iter (maybe empty), stage c done
        __syncthreads();   // stage c visible; all warps finished stage (c+3)%4 reads

        // Refill the slot freed by chunk c-1 with chunk c+3 (commit ALWAYS so
        // the group count per iteration is uniform and CP_WAIT(2) stays exact)
        if (c + 3 < nch)
            stage_load(Ah, Bh, K, (c + 3) << 6,
                       sbase + (uint32_t)(((c + 3) & 3) * STG_BYTES), tid);
        CP_COMMIT();

        const uint32_t tb = sbase + (uint32_t)((c & 3) * STG_BYTES);
#pragma unroll
        for (int ks = 0; ks < 4; ks++) {
            uint32_t ah[2][4];
            const uint32_t acol = (uint32_t)(((ks << 1) + a_chs) << 4);
            const uint32_t bcol = (uint32_t)(((ks << 1) + b_chs) << 4);
#pragma unroll
            for (int mi = 0; mi < 2; mi++) {
                const uint32_t ad = tb + (uint32_t)((a_row + mi * 16) * RS) + acol;
                ldm_x4(ah[mi][0], ah[mi][1], ah[mi][2], ah[mi][3], ad);
            }
#pragma unroll
            for (int pr = 0; pr < 4; pr++) {
                uint32_t bh[4];
                const uint32_t bd = tb + (uint32_t)(B_OFF + (b_row + pr * 16) * RS) + bcol;
                ldm_x4(bh[0], bh[1], bh[2], bh[3], bd);
#pragma unroll
                for (int mi = 0; mi < 2; mi++)
#pragma unroll
                    for (int q = 0; q < 2; q++) {
                        const int of = q << 1;
                        float* d = acc[mi][pr * 2 + q];
                        mma_f16(d[0], d[1], d[2], d[3],
                                ah[mi][0], ah[mi][1], ah[mi][2], ah[mi][3],
                                bh[of], bh[of + 1]);
                    }
            }
        }
    }

    // Epilogue: direct register -> global stores
    const int t4 = lid >> 2;         // 0..7  row within 8
    const int t2 = (lid & 3) << 1;   // col pair
#pragma unroll
    for (int ni = 0; ni < 8; ni++) {
        const int gcol = blockIdx.x * 256 + wn * 64 + ni * 8 + t2;
        float bi0 = 0.0f, bi1 = 0.0f;
        if (bias) { bi0 = bias[gcol]; bi1 = bias[gcol + 1]; }
#pragma unroll
        for (int mi = 0; mi < 2; mi++) {
            const int grow = blockIdx.y * 128 + wm * 32 + mi * 16 + t4;
            const float* d = acc[mi][ni];
            float v00 = fmaf(alpha, d[0], bi0);
            float v01 = fmaf(alpha, d[1], bi1);
            float v10 = fmaf(alpha, d[2], bi0);
            float v11 = fmaf(alpha, d[3], bi1);
            const size_t o0 = zC + (size_t)grow * N + gcol;
            const size_t o1 = o0 + (size_t)8 * N;
            if (C) {
                *reinterpret_cast<float2*>(C + o0) = make_float2(v00, v01);
                *reinterpret_cast<float2*>(C + o1) = make_float2(v10, v11);
            }
            if (Ch) {
                *reinterpret_cast<__half2*>(Ch + o0) =
                    __halves2half2(__float2half(v00), __float2half(v01));
                *reinterpret_cast<__half2*>(Ch + o1) =
                    __halves2half2(__float2half(v10), __float2half(v11));
            }
        }
    }
}

// ---------------------------------------------------------------------------
// fp32 -> fp16 convert, vectorized by 4
// ---------------------------------------------------------------------------
__global__ void __launch_bounds__(256)
cvt_kernel(const float* __restrict__ x, __half* __restrict__ hi, int n4)
{
    int i = blockIdx.x * 256 + threadIdx.x;
    if (i >= n4) return;
    float4 v = reinterpret_cast<const float4*>(x)[i];
    reinterpret_cast<__half2*>(hi)[2 * i] =
        __halves2half2(__float2half(v.x), __float2half(v.y));
    reinterpret_cast<__half2*>(hi)[2 * i + 1] =
        __halves2half2(__float2half(v.z), __float2half(v.w));
}

// ---------------------------------------------------------------------------
// V [b][s][h] fp32 -> Vt [b][h][s] fp16 (transpose, single rounding)
// ---------------------------------------------------------------------------
__global__ void __launch_bounds__(256)
transpose_h_kernel(const float* __restrict__ V, __half* __restrict__ Th)
{
    __shared__ float tile[32][33];
    const int b = blockIdx.z;
    const int h0 = blockIdx.x * 32, s0 = blockIdx.y * 32;
    const int tx = threadIdx.x & 31, ty = threadIdx.x >> 5; // 32 x 8
    const float* Vb = V + (size_t)b * SEQ * HID;
#pragma unroll
    for (int j = 0; j < 32; j += 8)
        tile[ty + j][tx] = Vb[(size_t)(s0 + ty + j) * HID + h0 + tx];
    __syncthreads();
    __half* Thb = Th + (size_t)b * HID * SEQ;
#pragma unroll
    for (int j = 0; j < 32; j += 8) {
        float v = tile[tx][ty + j];
        Thb[(size_t)(h0 + ty + j) * SEQ + s0 + tx] = __float2half(v);
    }
}

// ---------------------------------------------------------------------------
// Row softmax (2048 cols), fp16 output
// ---------------------------------------------------------------------------
__global__ void __launch_bounds__(256)
softmax_h_kernel(const float* __restrict__ Sc, __half* __restrict__ Ph)
{
    __shared__ float red[256];
    const float* row = Sc + (size_t)blockIdx.x * SEQ;
    const int tid = threadIdx.x;

    float4 v0 = reinterpret_cast<const float4*>(row)[tid];
    float4 v1 = reinterpret_cast<const float4*>(row)[tid + 256];

    float m = fmaxf(fmaxf(fmaxf(v0.x, v0.y), fmaxf(v0.z, v0.w)),
                    fmaxf(fmaxf(v1.x, v1.y), fmaxf(v1.z, v1.w)));
    red[tid] = m;
    __syncthreads();
#pragma unroll
    for (int s = 128; s > 0; s >>= 1) {
        if (tid < s) red[tid] = fmaxf(red[tid], red[tid + s]);
        __syncthreads();
    }
    m = red[0];
    __syncthreads();

    v0.x = __expf(v0.x - m); v0.y = __expf(v0.y - m);
    v0.z = __expf(v0.z - m); v0.w = __expf(v0.w - m);
    v1.x = __expf(v1.x - m); v1.y = __expf(v1.y - m);
    v1.z = __expf(v1.z - m); v1.w = __expf(v1.w - m);

    red[tid] = v0.x + v0.y + v0.z + v0.w + v1.x + v1.y + v1.z + v1.w;
    __syncthreads();
#pragma unroll
    for (int s = 128; s > 0; s >>= 1) {
        if (tid < s) red[tid] += red[tid + s];
        __syncthreads();
    }
    const float inv = 1.0f / red[0];

    __half2* H = reinterpret_cast<__half2*>(Ph + (size_t)blockIdx.x * SEQ);
    H[2 * tid] = __halves2half2(__float2half(v0.x * inv), __float2half(v0.y * inv));
    H[2 * tid + 1] = __halves2half2(__float2half(v0.z * inv), __float2half(v0.w * inv));
    H[512 + 2 * tid] = __halves2half2(__float2half(v1.x * inv), __float2half(v1.y * inv));
    H[512 + 2 * tid + 1] = __halves2half2(__float2half(v1.z * inv), __float2half(v1.w * inv));
}

// ---------------------------------------------------------------------------
// Launch
// ---------------------------------------------------------------------------
extern "C" void kernel_launch(void* const* d_in, const int* in_sizes, int n_in,
                              void* d_out, int out_size)
{
    const float* X  = (const float*)d_in[0];
    const float* Wq = (const float*)d_in[1];
    const float* bq = (const float*)d_in[2];
    const float* Wk = (const float*)d_in[3];
    const float* bk = (const float*)d_in[4];
    const float* Wv = (const float*)d_in[5];
    const float* bv = (const float*)d_in[6];
    float* out = (float*)d_out;

    __half *Xh, *Wh, *Qh, *Kh, *Vth, *Ph;
    float *V, *Sc;
    cudaGetSymbolAddress((void**)&Xh, g_Xh);
    cudaGetSymbolAddress((void**)&Wh, g_Wh);
    cudaGetSymbolAddress((void**)&Qh, g_Qh);
    cudaGetSymbolAddress((void**)&Kh, g_Kh);
    cudaGetSymbolAddress((void**)&V,  g_V);
    cudaGetSymbolAddress((void**)&Vth, g_Vth);
    cudaGetSymbolAddress((void**)&Sc, g_Sc);
    cudaGetSymbolAddress((void**)&Ph, g_Ph);

    cudaFuncSetAttribute(gemm1_mma_kernel,
                         cudaFuncAttributeMaxDynamicSharedMemorySize, SMEM_BYTES);

    // Convert inputs to fp16 (single rounding everywhere)
    {
        int n4 = ROWS * HID / 4;
        cvt_kernel<<<(n4 + 255) / 256, 256>>>(X, Xh, n4);
        int w4 = HID * HID / 4;
        cvt_kernel<<<(w4 + 255) / 256, 256>>>(Wq, Wh, w4);
        cvt_kernel<<<(w4 + 255) / 256, 256>>>(Wk, Wh + (size_t)HID * HID, w4);
        cvt_kernel<<<(w4 + 255) / 256, 256>>>(Wv, Wh + (size_t)2 * HID * HID, w4);
    }

    dim3 blk(512);

    // QKV projections: [8192,1024] = X @ W^T + b
    dim3 gq(HID / 256, ROWS / 128, 1);
    gemm1_mma_kernel<<<gq, blk, SMEM_BYTES>>>(Xh, Wh, bq,
                                              nullptr, Qh,
                                              HID, HID, 1.0f, 0, 0, 0);
    gemm1_mma_kernel<<<gq, blk, SMEM_BYTES>>>(Xh, Wh + (size_t)HID * HID, bk,
                                              nullptr, Kh,
                                              HID, HID, 1.0f, 0, 0, 0);
    gemm1_mma_kernel<<<gq, blk, SMEM_BYTES>>>(Xh, Wh + (size_t)2 * HID * HID, bv,
                                              V, nullptr,
                                              HID, HID, 1.0f, 0, 0, 0);

    // V -> Vt (per batch: [h][s])
    {
        dim3 gt(HID / 32, SEQ / 32, NB);
        transpose_h_kernel<<<gt, 256>>>(V, Vth);
    }

    // scores[b] = Q[b] @ K[b]^T / 32
    dim3 gs(SEQ / 256, SEQ / 128, NB);
    gemm1_mma_kernel<<<gs, blk, SMEM_BYTES>>>(Qh, Kh, nullptr,
                                              Sc, nullptr,
                                              SEQ, HID, 0.03125f,
                                              (size_t)SEQ * HID, (size_t)SEQ * HID,
                                              (size_t)SEQ * SEQ);

    // softmax -> fp16 P
    softmax_h_kernel<<<NB * SEQ, 256>>>(Sc, Ph);

    // out[b] = P[b] @ Vt[b]^T  (Vt is [N=hid, K=seq] K-major)
    dim3 ga(HID / 256, SEQ / 128, NB);
    gemm1_mma_kernel<<<ga, blk, SMEM_BYTES>>>(Ph, Vth, nullptr,
                                              out, nullptr,
                                              HID, SEQ, 1.0f,
                                              (size_t)SEQ * SEQ, (size_t)SEQ * HID,
                                              (size_t)SEQ * HID);
}